// round 11
// baseline (speedup 1.0000x reference)
#include <cuda_runtime.h>
#include <math.h>

#define B_ 4
#define T_ 256
#define N_ 48
#define F_ 4
#define H_ 64
#define K_ 4
#define E_ 192
#define LH_ 512
#define C_ 8
#define G_ (B_*T_)     // 1024
#define KH_ (K_*H_)    // 256
#define KHP_ (KH_+1)
#define NH_ (N_*H_)    // 3072
#define G4_ (4*LH_)    // 2048
#define NEG_SLOPE 0.2f

#define LCTAS 64
#define LTHR 128
#define JPC 8
#define WPAD 516       // 512+4: 16B-aligned rows, conflict-free LDS.128

// ---------------- scratch ----------------------------------------------------
__device__ float g_h1[G_*N_*KH_];
__device__ float g_seq[G_*NH_];
__device__ float g_xw[G_*G4_];
__device__ float g_hbuf[2][B_][LH_];
__device__ int   g_coff[N_+1];
__device__ int   g_ceid[E_];
__device__ unsigned g_cnt;
__device__ volatile unsigned g_gen;
__device__ unsigned g_scnt[T_];

// ---------------- deterministic CSR build ------------------------------------
__global__ void build_csr_kernel(const int* __restrict__ ei)
{
    __shared__ int sdst[E_];
    __shared__ int sdeg[N_];
    __shared__ int soff[N_+1];
    int tid = threadIdx.x;
    for (int e = tid; e < E_; e += blockDim.x) sdst[e] = ei[E_ + e];
    __syncthreads();
    for (int n = tid; n < N_; n += blockDim.x) {
        int d = 0;
        for (int e = 0; e < E_; e++) d += (sdst[e] == n);
        sdeg[n] = d;
    }
    __syncthreads();
    if (tid == 0) {
        int acc = 0;
        for (int n = 0; n < N_; n++) { soff[n] = acc; acc += sdeg[n]; }
        soff[N_] = acc;
    }
    __syncthreads();
    for (int n = tid; n < N_; n += blockDim.x) {
        int p = soff[n];
        for (int e = 0; e < E_; e++) if (sdst[e] == n) g_ceid[p++] = e;
    }
    for (int n = tid; n <= N_; n += blockDim.x) g_coff[n] = soff[n];
}

// ---------------- GAT layer 1 ------------------------------------------------
__global__ __launch_bounds__(256) void gat1_kernel(
    const float* __restrict__ x, const int* __restrict__ ei,
    const float* __restrict__ Wl, const float* __restrict__ Wr,
    const float* __restrict__ att, const float* __restrict__ bias)
{
    extern __shared__ float sm[];
    float* xl   = sm;
    float* xr   = xl + N_*KHP_;
    float* wl   = xr + N_*KHP_;
    float* wr   = wl + F_*KH_;
    float* satt = wr + F_*KH_;
    float* sb   = satt + KH_;
    float* sx   = sb + KH_;
    float* se   = sx + N_*F_;
    int* ssrc = (int*)(se + E_*K_);
    int* sdst = ssrc + E_;
    int* soff = sdst + E_;
    int* seid = soff + (N_+1);

    int g = blockIdx.x;
    int tid = threadIdx.x;

    for (int i = tid; i < F_*KH_; i += 256) { wl[i] = Wl[i]; wr[i] = Wr[i]; }
    satt[tid] = att[tid];
    sb[tid] = bias[tid];
    for (int i = tid; i < N_*F_; i += 256) sx[i] = x[(size_t)g*N_*F_ + i];
    for (int i = tid; i < E_; i += 256) { ssrc[i] = ei[i]; sdst[i] = ei[E_+i]; seid[i] = g_ceid[i]; }
    for (int i = tid; i <= N_; i += 256) soff[i] = g_coff[i];
    __syncthreads();

    const int o = tid;
    for (int n = 0; n < N_; n++) {
        float al = 0.f, ar = 0.f;
        #pragma unroll
        for (int f = 0; f < F_; f++) {
            float xv = sx[n*F_ + f];
            al += xv * wl[f*KH_ + o];
            ar += xv * wr[f*KH_ + o];
        }
        xl[n*KHP_ + o] = al;
        xr[n*KHP_ + o] = ar;
    }
    __syncthreads();

    for (int idx = tid; idx < E_*K_; idx += 256) {
        int e = idx >> 2, k = idx & 3;
        const float* pl = xl + ssrc[e]*KHP_ + k*H_;
        const float* pr = xr + sdst[e]*KHP_ + k*H_;
        const float* pa = satt + k*H_;
        float acc = 0.f;
        #pragma unroll 8
        for (int h = 0; h < H_; h++) {
            float v = pl[h] + pr[h];
            v = v > 0.f ? v : NEG_SLOPE * v;
            acc += v * pa[h];
        }
        se[idx] = acc;
    }
    __syncthreads();

    for (int idx = tid; idx < N_*K_; idx += 256) {
        int n = idx >> 2, k = idx & 3;
        int a0 = soff[n], a1 = soff[n+1];
        float mx = -1e30f;
        for (int a = a0; a < a1; a++) mx = fmaxf(mx, se[seid[a]*K_ + k]);
        float s = 0.f;
        for (int a = a0; a < a1; a++) s += expf(se[seid[a]*K_ + k] - mx);
        float inv = 1.f / (s + 1e-16f);
        for (int a = a0; a < a1; a++) {
            int j = seid[a]*K_ + k;
            se[j] = expf(se[j] - mx) * inv;
        }
    }
    __syncthreads();

    int k = o >> 6;
    float* outp = g_h1 + (size_t)g*N_*KH_;
    for (int n = 0; n < N_; n++) {
        int a0 = soff[n], a1 = soff[n+1];
        float acc = 0.f;
        for (int a = a0; a < a1; a++) {
            int e = seid[a];
            acc += se[e*K_ + k] * xl[ssrc[e]*KHP_ + o];
        }
        outp[n*KH_ + o] = fmaxf(acc + sb[o], 0.f);
    }
}

// ---------------- GAT layer 2 (fused fp32, proven) ----------------------------
__global__ __launch_bounds__(256) void gat2_kernel(
    const int* __restrict__ ei,
    const float* __restrict__ Wl, const float* __restrict__ Wr,
    const float* __restrict__ att, const float* __restrict__ bias)
{
    extern __shared__ float sm[];
    float* sh_in = sm;
    float* xl    = sh_in + N_*KH_;
    float* xr    = xl + N_*KHP_;
    float* satt  = xr + N_*KHP_;
    float* sb    = satt + KH_;
    float* se    = sb + H_;
    int* ssrc = (int*)(se + E_*K_);
    int* sdst = ssrc + E_;
    int* soff = sdst + E_;
    int* seid = soff + (N_+1);

    int g = blockIdx.x;
    int tid = threadIdx.x;

    const float* h1p = g_h1 + (size_t)g*N_*KH_;
    for (int i = tid; i < N_*KH_; i += 256) sh_in[i] = h1p[i];
    satt[tid] = att[tid];
    if (tid < H_) sb[tid] = bias[tid];
    for (int i = tid; i < E_; i += 256) { ssrc[i] = ei[i]; sdst[i] = ei[E_+i]; seid[i] = g_ceid[i]; }
    for (int i = tid; i <= N_; i += 256) soff[i] = g_coff[i];
    __syncthreads();

    const int o = tid;
    {
        float acc[N_];
        #pragma unroll
        for (int n = 0; n < N_; n++) acc[n] = 0.f;
        #pragma unroll 2
        for (int i = 0; i < KH_; i++) {
            float w = Wl[i*KH_ + o];
            #pragma unroll
            for (int n = 0; n < N_; n++) acc[n] += sh_in[n*KH_ + i] * w;
        }
        #pragma unroll
        for (int n = 0; n < N_; n++) xl[n*KHP_ + o] = acc[n];
    }
    {
        float acc[N_];
        #pragma unroll
        for (int n = 0; n < N_; n++) acc[n] = 0.f;
        #pragma unroll 2
        for (int i = 0; i < KH_; i++) {
            float w = Wr[i*KH_ + o];
            #pragma unroll
            for (int n = 0; n < N_; n++) acc[n] += sh_in[n*KH_ + i] * w;
        }
        #pragma unroll
        for (int n = 0; n < N_; n++) xr[n*KHP_ + o] = acc[n];
    }
    __syncthreads();

    for (int idx = tid; idx < E_*K_; idx += 256) {
        int e = idx >> 2, k = idx & 3;
        const float* pl = xl + ssrc[e]*KHP_ + k*H_;
        const float* pr = xr + sdst[e]*KHP_ + k*H_;
        const float* pa = satt + k*H_;
        float acc = 0.f;
        #pragma unroll 8
        for (int h = 0; h < H_; h++) {
            float v = pl[h] + pr[h];
            v = v > 0.f ? v : NEG_SLOPE * v;
            acc += v * pa[h];
        }
        se[idx] = acc;
    }
    __syncthreads();

    for (int idx = tid; idx < N_*K_; idx += 256) {
        int n = idx >> 2, k = idx & 3;
        int a0 = soff[n], a1 = soff[n+1];
        float mx = -1e30f;
        for (int a = a0; a < a1; a++) mx = fmaxf(mx, se[seid[a]*K_ + k]);
        float s = 0.f;
        for (int a = a0; a < a1; a++) s += expf(se[seid[a]*K_ + k] - mx);
        float inv = 1.f / (s + 1e-16f);
        for (int a = a0; a < a1; a++) {
            int j = seid[a]*K_ + k;
            se[j] = expf(se[j] - mx) * inv;
        }
    }
    __syncthreads();

    for (int idx = tid; idx < N_*H_; idx += 256) {
        int n = idx >> 6, h = idx & 63;
        int a0 = soff[n], a1 = soff[n+1];
        float acc = 0.f;
        for (int a = a0; a < a1; a++) {
            int e = seid[a]; int s = ssrc[e];
            #pragma unroll
            for (int k2 = 0; k2 < K_; k2++)
                acc += se[e*K_ + k2] * xl[s*KHP_ + k2*H_ + h];
        }
        float v = acc * 0.25f + sb[h];
        g_seq[(size_t)g*NH_ + n*H_ + h] = fmaxf(v, 0.f);
    }
}

// ---------------- xw GEMM (proven 64x64x32 fp32) ------------------------------
#define BM 64
#define BN 64
#define BK 32
#define BMP (BM+4)
#define BNP (BN+4)
__global__ __launch_bounds__(256) void xw_gemm_kernel(
    const float* __restrict__ W_ih,
    const float* __restrict__ b_ih, const float* __restrict__ b_hh)
{
    __shared__ float As[BK][BMP];
    __shared__ float Bs[BK][BNP];
    int bn = blockIdx.x, bm = blockIdx.y;
    int tid = threadIdx.x;
    int tx = tid & 15, ty = tid >> 4;
    float acc[4][4] = {};
    const float* A0 = g_seq + (size_t)(bm*BM)*NH_;
    const float* B0 = W_ih + (size_t)(bn*BN)*NH_;
    int lr = tid >> 3;
    int lc = (tid & 7) * 4;

    for (int k0 = 0; k0 < NH_; k0 += BK) {
        #pragma unroll
        for (int half = 0; half < 2; half++) {
            int r = lr + half*32;
            float4 a4 = *(const float4*)&A0[(size_t)r*NH_ + k0 + lc];
            As[lc+0][r] = a4.x; As[lc+1][r] = a4.y;
            As[lc+2][r] = a4.z; As[lc+3][r] = a4.w;
            float4 b4 = *(const float4*)&B0[(size_t)r*NH_ + k0 + lc];
            Bs[lc+0][r] = b4.x; Bs[lc+1][r] = b4.y;
            Bs[lc+2][r] = b4.z; Bs[lc+3][r] = b4.w;
        }
        __syncthreads();
        #pragma unroll
        for (int k = 0; k < BK; k++) {
            float4 av = *(const float4*)&As[k][ty*4];
            float4 bv = *(const float4*)&Bs[k][tx*4];
            float a[4] = {av.x, av.y, av.z, av.w};
            float b[4] = {bv.x, bv.y, bv.z, bv.w};
            #pragma unroll
            for (int i = 0; i < 4; i++)
                #pragma unroll
                for (int j = 0; j < 4; j++)
                    acc[i][j] += a[i] * b[j];
        }
        __syncthreads();
    }
    #pragma unroll
    for (int i = 0; i < 4; i++) {
        int r = bm*BM + ty*4 + i;
        int c = bn*BN + tx*4;
        float4 o;
        o.x = acc[i][0] + b_ih[c+0] + b_hh[c+0];
        o.y = acc[i][1] + b_ih[c+1] + b_hh[c+1];
        o.z = acc[i][2] + b_ih[c+2] + b_hh[c+2];
        o.w = acc[i][3] + b_ih[c+3] + b_hh[c+3];
        *(float4*)&g_xw[(size_t)r*G4_ + c] = o;
    }
}

// ---------------- persistent LSTM: R3 datapath + low-contention barrier -------
__device__ __forceinline__ float sigm(float x) { return 1.f / (1.f + expf(-x)); }

__device__ __forceinline__ void init_barrier()
{
    __syncthreads();
    if (threadIdx.x == 0) {
        unsigned my = g_gen;
        __threadfence();
        if (atomicAdd(&g_cnt, 1u) == LCTAS - 1) {
            atomicExch(&g_cnt, 0u);
            __threadfence();
            atomicAdd((unsigned*)&g_gen, 1u);
        } else {
            while (g_gen == my) { }
        }
    }
    __syncthreads();
}

__global__ __launch_bounds__(LTHR) void lstm_kernel(const float* __restrict__ W_hh)
{
    extern __shared__ float sm[];
    float* sw = sm;                      // 32 rows x WPAD
    float* sh = sw + 32*WPAD;            // B_*LH_ staged h

    int tid = threadIdx.x;
    int blk = blockIdx.x;
    int j0 = blk * JPC;

    for (int idx = tid; idx < 32*LH_; idx += LTHR) {
        int row = idx >> 9;
        int i = idx & 511;
        int gate = row >> 3, jj = row & 7;
        sw[row*WPAD + i] = W_hh[(size_t)(gate*LH_ + j0 + jj)*LH_ + i];
    }
    if (tid < T_/LCTAS) g_scnt[blk*(T_/LCTAS) + tid] = 0;
    for (int idx = tid; idx < B_*JPC; idx += LTHR) {
        int b = idx >> 3, jj = idx & 7;
        g_hbuf[0][b][j0 + jj] = 0.f;
    }
    __threadfence();
    init_barrier();

    const int b = tid >> 5;              // warp = batch
    const int lane = tid & 31;
    const int gate = lane >> 3, jj = lane & 7;
    const int row = gate*8 + jj;
    const float4* wv = (const float4*)(sw + row*WPAD);
    const float* xp = g_xw + (size_t)(b*T_)*G4_ + gate*LH_ + j0 + jj;
    float c = 0.f;

    for (int t = 0; t < T_; t++) {
        int p = t & 1;
        float4 hstage[4];
        #pragma unroll
        for (int q = 0; q < 4; q++)
            hstage[q] = __ldcg(((const float4*)&g_hbuf[p][0][0]) + tid + q*LTHR);
        float xval = __ldcg(xp + (size_t)t*G4_);
        #pragma unroll
        for (int q = 0; q < 4; q++)
            ((float4*)sh)[tid + q*LTHR] = hstage[q];
        __syncthreads();

        const float4* hv = (const float4*)(sh + b*LH_);
        float4 a0 = make_float4(0.f,0.f,0.f,0.f);
        float4 a1 = make_float4(0.f,0.f,0.f,0.f);
        #pragma unroll 8
        for (int i = 0; i < LH_/8; i++) {
            float4 w0 = wv[2*i],   h0 = hv[2*i];
            float4 w1 = wv[2*i+1], h1 = hv[2*i+1];
            a0.x += w0.x*h0.x; a0.y += w0.y*h0.y; a0.z += w0.z*h0.z; a0.w += w0.w*h0.w;
            a1.x += w1.x*h1.x; a1.y += w1.y*h1.y; a1.z += w1.z*h1.z; a1.w += w1.w*h1.w;
        }
        float val = ((a0.x+a0.y)+(a0.z+a0.w)) + ((a1.x+a1.y)+(a1.z+a1.w)) + xval;

        float gi = __shfl_sync(0xffffffffu, val, jj);
        float gf = __shfl_sync(0xffffffffu, val, 8 + jj);
        float gg = __shfl_sync(0xffffffffu, val, 16 + jj);
        float go = __shfl_sync(0xffffffffu, val, 24 + jj);
        if (lane < 8) {
            c = sigm(gf)*c + sigm(gi)*tanhf(gg);
            float h = sigm(go)*tanhf(c);
            g_hbuf[p ^ 1][b][j0 + lane] = h;
        }
        __syncthreads();
        if (t < T_-1) {
            // low-contention barrier: ONE thread arrives and polls (with backoff),
            // CTA released via syncthreads. Avoids 256 warps hammering one L2 line.
            if (tid == 0) {
                __threadfence();
                atomicAdd(&g_scnt[t], 1u);
                unsigned* cp = &g_scnt[t];
                unsigned v;
                while (1) {
                    asm volatile("ld.acquire.gpu.global.u32 %0, [%1];"
                                 : "=r"(v) : "l"(cp) : "memory");
                    if (v >= LCTAS) break;
                    __nanosleep(128);
                }
                __threadfence();
            }
            __syncthreads();
        }
    }
}

// ---------------- final fc -----------------------------------------------------
__global__ void fc_kernel(const float* __restrict__ fc_w,
                          const float* __restrict__ fc_b,
                          float* __restrict__ out)
{
    int tid = threadIdx.x;
    if (tid < B_*C_) {
        int b = tid >> 3, c = tid & 7;
        const float* h = g_hbuf[0][b];
        const float* w = fc_w + c*LH_;
        float acc = 0.f;
        for (int j = 0; j < LH_; j++) acc += h[j] * w[j];
        out[b*C_ + c] = acc + fc_b[c];
    }
}

// ---------------- launch -------------------------------------------------------
extern "C" void kernel_launch(void* const* d_in, const int* in_sizes, int n_in,
                              void* d_out, int out_size)
{
    (void)in_sizes; (void)n_in; (void)out_size;
    const float* x    = (const float*)d_in[0];
    const int*   ei   = (const int*)d_in[1];
    const float* Wl1  = (const float*)d_in[2];
    const float* Wr1  = (const float*)d_in[3];
    const float* att1 = (const float*)d_in[4];
    const float* b1   = (const float*)d_in[5];
    const float* Wl2  = (const float*)d_in[6];
    const float* Wr2  = (const float*)d_in[7];
    const float* att2 = (const float*)d_in[8];
    const float* b2   = (const float*)d_in[9];
    const float* W_ih = (const float*)d_in[10];
    const float* W_hh = (const float*)d_in[11];
    const float* b_ih = (const float*)d_in[12];
    const float* b_hh = (const float*)d_in[13];
    const float* fc_w = (const float*)d_in[14];
    const float* fc_b = (const float*)d_in[15];
    float* out = (float*)d_out;

    const size_t sm1 = (size_t)(2*N_*KHP_ + 2*F_*KH_ + 2*KH_ + N_*F_ + E_*K_) * 4
                     + (size_t)(2*E_ + (N_+1) + E_) * 4;
    const size_t sm2 = (size_t)(N_*KH_ + 2*N_*KHP_ + KH_ + H_ + E_*K_) * 4
                     + (size_t)(2*E_ + (N_+1) + E_) * 4;
    const size_t sml = (size_t)(32*WPAD + B_*LH_) * 4;

    cudaFuncSetAttribute(gat1_kernel, cudaFuncAttributeMaxDynamicSharedMemorySize, (int)sm1);
    cudaFuncSetAttribute(gat2_kernel, cudaFuncAttributeMaxDynamicSharedMemorySize, (int)sm2);
    cudaFuncSetAttribute(lstm_kernel, cudaFuncAttributeMaxDynamicSharedMemorySize, (int)sml);

    build_csr_kernel<<<1, 64>>>(ei);
    gat1_kernel<<<G_, 256, sm1>>>(x, ei, Wl1, Wr1, att1, b1);
    gat2_kernel<<<G_, 256, sm2>>>(ei, Wl2, Wr2, att2, b2);
    dim3 gx(G4_/BN, G_/BM);
    xw_gemm_kernel<<<gx, 256>>>(W_ih, b_ih, b_hh);
    lstm_kernel<<<LCTAS, LTHR, sml>>>(W_hh);
    fc_kernel<<<1, 32>>>(fc_w, fc_b, out);
}

// round 12
// speedup vs baseline: 1.2219x; 1.2219x over previous
#include <cuda_runtime.h>
#include <cuda_fp16.h>
#include <math.h>

#define B_ 4
#define T_ 256
#define N_ 48
#define F_ 4
#define H_ 64
#define K_ 4
#define E_ 192
#define LH_ 512
#define C_ 8
#define G_ (B_*T_)     // 1024
#define KH_ (K_*H_)    // 256
#define KHP_ (KH_+1)
#define NH_ (N_*H_)    // 3072
#define G4_ (4*LH_)    // 2048
#define NEG_SLOPE 0.2f

#define CLU 16                 // CTAs per cluster (one cluster per batch)
#define LROWS 128              // W rows per CTA (32 j x 4 gates)
#define WROWB 1028             // fp16 row stride in bytes (512*2 + 4): conflict-free
#define SW_BYTES (LROWS*WROWB) // 131584

// ---------------- scratch ----------------------------------------------------
__device__ float g_h1[G_*N_*KH_];
__device__ float g_seq[G_*NH_];
__device__ float g_xw[G_*G4_];
__device__ float g_hbuf[2][B_][LH_];
__device__ int   g_coff[N_+1];
__device__ int   g_ceid[E_];

// ---------------- deterministic CSR build ------------------------------------
__global__ void build_csr_kernel(const int* __restrict__ ei)
{
    __shared__ int sdst[E_];
    __shared__ int sdeg[N_];
    __shared__ int soff[N_+1];
    int tid = threadIdx.x;
    for (int e = tid; e < E_; e += blockDim.x) sdst[e] = ei[E_ + e];
    __syncthreads();
    for (int n = tid; n < N_; n += blockDim.x) {
        int d = 0;
        for (int e = 0; e < E_; e++) d += (sdst[e] == n);
        sdeg[n] = d;
    }
    __syncthreads();
    if (tid == 0) {
        int acc = 0;
        for (int n = 0; n < N_; n++) { soff[n] = acc; acc += sdeg[n]; }
        soff[N_] = acc;
    }
    __syncthreads();
    for (int n = tid; n < N_; n += blockDim.x) {
        int p = soff[n];
        for (int e = 0; e < E_; e++) if (sdst[e] == n) g_ceid[p++] = e;
    }
    for (int n = tid; n <= N_; n += blockDim.x) g_coff[n] = soff[n];
}

// ---------------- GAT layer 1 ------------------------------------------------
__global__ __launch_bounds__(256) void gat1_kernel(
    const float* __restrict__ x, const int* __restrict__ ei,
    const float* __restrict__ Wl, const float* __restrict__ Wr,
    const float* __restrict__ att, const float* __restrict__ bias)
{
    extern __shared__ float sm[];
    float* xl   = sm;
    float* xr   = xl + N_*KHP_;
    float* wl   = xr + N_*KHP_;
    float* wr   = wl + F_*KH_;
    float* satt = wr + F_*KH_;
    float* sb   = satt + KH_;
    float* sx   = sb + KH_;
    float* se   = sx + N_*F_;
    int* ssrc = (int*)(se + E_*K_);
    int* sdst = ssrc + E_;
    int* soff = sdst + E_;
    int* seid = soff + (N_+1);

    int g = blockIdx.x;
    int tid = threadIdx.x;

    for (int i = tid; i < F_*KH_; i += 256) { wl[i] = Wl[i]; wr[i] = Wr[i]; }
    satt[tid] = att[tid];
    sb[tid] = bias[tid];
    for (int i = tid; i < N_*F_; i += 256) sx[i] = x[(size_t)g*N_*F_ + i];
    for (int i = tid; i < E_; i += 256) { ssrc[i] = ei[i]; sdst[i] = ei[E_+i]; seid[i] = g_ceid[i]; }
    for (int i = tid; i <= N_; i += 256) soff[i] = g_coff[i];
    __syncthreads();

    const int o = tid;
    for (int n = 0; n < N_; n++) {
        float al = 0.f, ar = 0.f;
        #pragma unroll
        for (int f = 0; f < F_; f++) {
            float xv = sx[n*F_ + f];
            al += xv * wl[f*KH_ + o];
            ar += xv * wr[f*KH_ + o];
        }
        xl[n*KHP_ + o] = al;
        xr[n*KHP_ + o] = ar;
    }
    __syncthreads();

    for (int idx = tid; idx < E_*K_; idx += 256) {
        int e = idx >> 2, k = idx & 3;
        const float* pl = xl + ssrc[e]*KHP_ + k*H_;
        const float* pr = xr + sdst[e]*KHP_ + k*H_;
        const float* pa = satt + k*H_;
        float acc = 0.f;
        #pragma unroll 8
        for (int h = 0; h < H_; h++) {
            float v = pl[h] + pr[h];
            v = v > 0.f ? v : NEG_SLOPE * v;
            acc += v * pa[h];
        }
        se[idx] = acc;
    }
    __syncthreads();

    for (int idx = tid; idx < N_*K_; idx += 256) {
        int n = idx >> 2, k = idx & 3;
        int a0 = soff[n], a1 = soff[n+1];
        float mx = -1e30f;
        for (int a = a0; a < a1; a++) mx = fmaxf(mx, se[seid[a]*K_ + k]);
        float s = 0.f;
        for (int a = a0; a < a1; a++) s += expf(se[seid[a]*K_ + k] - mx);
        float inv = 1.f / (s + 1e-16f);
        for (int a = a0; a < a1; a++) {
            int j = seid[a]*K_ + k;
            se[j] = expf(se[j] - mx) * inv;
        }
    }
    __syncthreads();

    int k = o >> 6;
    float* outp = g_h1 + (size_t)g*N_*KH_;
    for (int n = 0; n < N_; n++) {
        int a0 = soff[n], a1 = soff[n+1];
        float acc = 0.f;
        for (int a = a0; a < a1; a++) {
            int e = seid[a];
            acc += se[e*K_ + k] * xl[ssrc[e]*KHP_ + o];
        }
        outp[n*KH_ + o] = fmaxf(acc + sb[o], 0.f);
    }
}

// ---------------- GAT layer 2 (fused fp32, proven) ----------------------------
__global__ __launch_bounds__(256) void gat2_kernel(
    const int* __restrict__ ei,
    const float* __restrict__ Wl, const float* __restrict__ Wr,
    const float* __restrict__ att, const float* __restrict__ bias)
{
    extern __shared__ float sm[];
    float* sh_in = sm;
    float* xl    = sh_in + N_*KH_;
    float* xr    = xl + N_*KHP_;
    float* satt  = xr + N_*KHP_;
    float* sb    = satt + KH_;
    float* se    = sb + H_;
    int* ssrc = (int*)(se + E_*K_);
    int* sdst = ssrc + E_;
    int* soff = sdst + E_;
    int* seid = soff + (N_+1);

    int g = blockIdx.x;
    int tid = threadIdx.x;

    const float* h1p = g_h1 + (size_t)g*N_*KH_;
    for (int i = tid; i < N_*KH_; i += 256) sh_in[i] = h1p[i];
    satt[tid] = att[tid];
    if (tid < H_) sb[tid] = bias[tid];
    for (int i = tid; i < E_; i += 256) { ssrc[i] = ei[i]; sdst[i] = ei[E_+i]; seid[i] = g_ceid[i]; }
    for (int i = tid; i <= N_; i += 256) soff[i] = g_coff[i];
    __syncthreads();

    const int o = tid;
    {
        float acc[N_];
        #pragma unroll
        for (int n = 0; n < N_; n++) acc[n] = 0.f;
        #pragma unroll 2
        for (int i = 0; i < KH_; i++) {
            float w = Wl[i*KH_ + o];
            #pragma unroll
            for (int n = 0; n < N_; n++) acc[n] += sh_in[n*KH_ + i] * w;
        }
        #pragma unroll
        for (int n = 0; n < N_; n++) xl[n*KHP_ + o] = acc[n];
    }
    {
        float acc[N_];
        #pragma unroll
        for (int n = 0; n < N_; n++) acc[n] = 0.f;
        #pragma unroll 2
        for (int i = 0; i < KH_; i++) {
            float w = Wr[i*KH_ + o];
            #pragma unroll
            for (int n = 0; n < N_; n++) acc[n] += sh_in[n*KH_ + i] * w;
        }
        #pragma unroll
        for (int n = 0; n < N_; n++) xr[n*KHP_ + o] = acc[n];
    }
    __syncthreads();

    for (int idx = tid; idx < E_*K_; idx += 256) {
        int e = idx >> 2, k = idx & 3;
        const float* pl = xl + ssrc[e]*KHP_ + k*H_;
        const float* pr = xr + sdst[e]*KHP_ + k*H_;
        const float* pa = satt + k*H_;
        float acc = 0.f;
        #pragma unroll 8
        for (int h = 0; h < H_; h++) {
            float v = pl[h] + pr[h];
            v = v > 0.f ? v : NEG_SLOPE * v;
            acc += v * pa[h];
        }
        se[idx] = acc;
    }
    __syncthreads();

    for (int idx = tid; idx < N_*K_; idx += 256) {
        int n = idx >> 2, k = idx & 3;
        int a0 = soff[n], a1 = soff[n+1];
        float mx = -1e30f;
        for (int a = a0; a < a1; a++) mx = fmaxf(mx, se[seid[a]*K_ + k]);
        float s = 0.f;
        for (int a = a0; a < a1; a++) s += expf(se[seid[a]*K_ + k] - mx);
        float inv = 1.f / (s + 1e-16f);
        for (int a = a0; a < a1; a++) {
            int j = seid[a]*K_ + k;
            se[j] = expf(se[j] - mx) * inv;
        }
    }
    __syncthreads();

    for (int idx = tid; idx < N_*H_; idx += 256) {
        int n = idx >> 6, h = idx & 63;
        int a0 = soff[n], a1 = soff[n+1];
        float acc = 0.f;
        for (int a = a0; a < a1; a++) {
            int e = seid[a]; int s = ssrc[e];
            #pragma unroll
            for (int k2 = 0; k2 < K_; k2++)
                acc += se[e*K_ + k2] * xl[s*KHP_ + k2*H_ + h];
        }
        float v = acc * 0.25f + sb[h];
        g_seq[(size_t)g*NH_ + n*H_ + h] = fmaxf(v, 0.f);
    }
}

// ---------------- xw GEMM (proven 64x64x32 fp32) ------------------------------
#define BM 64
#define BN 64
#define BK 32
#define BMP (BM+4)
#define BNP (BN+4)
__global__ __launch_bounds__(256) void xw_gemm_kernel(
    const float* __restrict__ W_ih,
    const float* __restrict__ b_ih, const float* __restrict__ b_hh)
{
    __shared__ float As[BK][BMP];
    __shared__ float Bs[BK][BNP];
    int bn = blockIdx.x, bm = blockIdx.y;
    int tid = threadIdx.x;
    int tx = tid & 15, ty = tid >> 4;
    float acc[4][4] = {};
    const float* A0 = g_seq + (size_t)(bm*BM)*NH_;
    const float* B0 = W_ih + (size_t)(bn*BN)*NH_;
    int lr = tid >> 3;
    int lc = (tid & 7) * 4;

    for (int k0 = 0; k0 < NH_; k0 += BK) {
        #pragma unroll
        for (int half = 0; half < 2; half++) {
            int r = lr + half*32;
            float4 a4 = *(const float4*)&A0[(size_t)r*NH_ + k0 + lc];
            As[lc+0][r] = a4.x; As[lc+1][r] = a4.y;
            As[lc+2][r] = a4.z; As[lc+3][r] = a4.w;
            float4 b4 = *(const float4*)&B0[(size_t)r*NH_ + k0 + lc];
            Bs[lc+0][r] = b4.x; Bs[lc+1][r] = b4.y;
            Bs[lc+2][r] = b4.z; Bs[lc+3][r] = b4.w;
        }
        __syncthreads();
        #pragma unroll
        for (int k = 0; k < BK; k++) {
            float4 av = *(const float4*)&As[k][ty*4];
            float4 bv = *(const float4*)&Bs[k][tx*4];
            float a[4] = {av.x, av.y, av.z, av.w};
            float b[4] = {bv.x, bv.y, bv.z, bv.w};
            #pragma unroll
            for (int i = 0; i < 4; i++)
                #pragma unroll
                for (int j = 0; j < 4; j++)
                    acc[i][j] += a[i] * b[j];
        }
        __syncthreads();
    }
    #pragma unroll
    for (int i = 0; i < 4; i++) {
        int r = bm*BM + ty*4 + i;
        int c = bn*BN + tx*4;
        float4 o;
        o.x = acc[i][0] + b_ih[c+0] + b_hh[c+0];
        o.y = acc[i][1] + b_ih[c+1] + b_hh[c+1];
        o.z = acc[i][2] + b_ih[c+2] + b_hh[c+2];
        o.w = acc[i][3] + b_ih[c+3] + b_hh[c+3];
        *(float4*)&g_xw[(size_t)r*G4_ + c] = o;
    }
}

// ---------------- cluster LSTM: DSMEM h-exchange, fp16 W in smem --------------
__device__ __forceinline__ float sigm(float x) { return 1.f / (1.f + expf(-x)); }

__device__ __forceinline__ unsigned smem_u32(const void* p)
{
    unsigned a;
    asm("{ .reg .u64 t; cvta.to.shared.u64 t, %1; cvt.u32.u64 %0, t; }"
        : "=r"(a) : "l"(p));
    return a;
}
__device__ __forceinline__ unsigned my_cluster_rank()
{
    unsigned r;
    asm("mov.u32 %0, %%cluster_ctarank;" : "=r"(r));
    return r;
}
__device__ __forceinline__ void dsmem_store_f32(unsigned laddr, unsigned rank, float v)
{
    asm volatile(
        "{ .reg .b32 ra; mapa.shared::cluster.u32 ra, %0, %1; "
        "st.shared::cluster.f32 [ra], %2; }"
        :: "r"(laddr), "r"(rank), "f"(v) : "memory");
}

__global__ __launch_bounds__(128, 1) void lstm_cluster_kernel(const float* __restrict__ W_hh)
{
    extern __shared__ char smc[];
    // layout: W fp16 rows [LROWS x WROWB bytes] | hbuf[2][512] f32 | sval[128] | htmp[32]
    float* hbuf = (float*)(smc + SW_BYTES);
    float* sval = hbuf + 2*LH_;
    float* htmp = sval + LROWS;

    const int tid  = threadIdx.x;
    const int b    = blockIdx.x / CLU;          // cluster == batch
    const unsigned rank = my_cluster_rank();    // 0..15
    const int j0   = rank * 32;

    // load W slice as fp16: smem row r <- W_hh row gate*LH_ + j0 + (r&31)
    for (int idx = tid; idx < LROWS*256; idx += 128) {
        int r  = idx >> 8;           // 0..127
        int i2 = idx & 255;          // half2 index
        int gate = r >> 5, jr = r & 31;
        float2 wv = *(const float2*)&W_hh[(size_t)(gate*LH_ + j0 + jr)*LH_ + i2*2];
        *(__half2*)(smc + r*WROWB + i2*4) = __floats2half2_rn(wv.x, wv.y);
    }
    // zero h buffer 0
    for (int i = tid; i < LH_; i += 128) hbuf[i] = 0.f;
    __syncthreads();

    const int row  = tid;                        // one W row per thread
    const int gate = row >> 5, jr = row & 31;
    const unsigned* wrow = (const unsigned*)(smc + row*WROWB);
    const float* xp = g_xw + (size_t)(b*T_)*G4_ + gate*LH_ + j0 + jr;
    const unsigned hbuf_addr = smem_u32(hbuf);

    float xval = __ldcg(xp);                     // t = 0 x-part
    float c = 0.f;                               // cell state (threads 0..31)

    for (int t = 0; t < T_; t++) {
        const float2* hv = (const float2*)(hbuf + (t & 1)*LH_);
        float a0 = 0.f, a1 = 0.f;
        #pragma unroll 8
        for (int i = 0; i < LH_/2; i++) {
            unsigned w2 = wrow[i];
            float2 wf = __half22float2(*(__half2*)&w2);
            float2 h2 = hv[i];
            a0 = fmaf(wf.x, h2.x, a0);
            a1 = fmaf(wf.y, h2.y, a1);
        }
        sval[row] = a0 + a1 + xval;
        __syncthreads();

        if (tid < 32) {
            float gi = sval[tid];
            float gf = sval[32 + tid];
            float gg = sval[64 + tid];
            float go = sval[96 + tid];
            c = sigm(gf)*c + sigm(gi)*tanhf(gg);
            float h = sigm(go)*tanhf(c);
            htmp[tid] = h;
            if (t == T_-1) g_hbuf[0][b][j0 + tid] = h;
        }
        __syncthreads();

        if (t < T_-1) {
            // broadcast my 32 h values into every cluster CTA's next buffer
            float v = htmp[tid & 31];
            unsigned dst = hbuf_addr + ((t + 1) & 1)*(LH_*4) + (j0 + (tid & 31))*4;
            #pragma unroll
            for (int q = 0; q < 4; q++)
                dsmem_store_f32(dst, q*4 + (tid >> 5), v);
            xval = __ldcg(xp + (size_t)(t + 1)*G4_);   // prefetch next x
            asm volatile("barrier.cluster.arrive.aligned;" ::: "memory");
            asm volatile("barrier.cluster.wait.aligned;" ::: "memory");
        }
    }
    // final cluster sync: no CTA exits while peers could still touch its smem
    asm volatile("barrier.cluster.arrive.aligned;" ::: "memory");
    asm volatile("barrier.cluster.wait.aligned;" ::: "memory");
}

// ---------------- final fc -----------------------------------------------------
__global__ void fc_kernel(const float* __restrict__ fc_w,
                          const float* __restrict__ fc_b,
                          float* __restrict__ out)
{
    int tid = threadIdx.x;
    if (tid < B_*C_) {
        int b = tid >> 3, c = tid & 7;
        const float* h = g_hbuf[0][b];
        const float* w = fc_w + c*LH_;
        float acc = 0.f;
        for (int j = 0; j < LH_; j++) acc += h[j] * w[j];
        out[b*C_ + c] = acc + fc_b[c];
    }
}

// ---------------- launch -------------------------------------------------------
extern "C" void kernel_launch(void* const* d_in, const int* in_sizes, int n_in,
                              void* d_out, int out_size)
{
    (void)in_sizes; (void)n_in; (void)out_size;
    const float* x    = (const float*)d_in[0];
    const int*   ei   = (const int*)d_in[1];
    const float* Wl1  = (const float*)d_in[2];
    const float* Wr1  = (const float*)d_in[3];
    const float* att1 = (const float*)d_in[4];
    const float* b1   = (const float*)d_in[5];
    const float* Wl2  = (const float*)d_in[6];
    const float* Wr2  = (const float*)d_in[7];
    const float* att2 = (const float*)d_in[8];
    const float* b2   = (const float*)d_in[9];
    const float* W_ih = (const float*)d_in[10];
    const float* W_hh = (const float*)d_in[11];
    const float* b_ih = (const float*)d_in[12];
    const float* b_hh = (const float*)d_in[13];
    const float* fc_w = (const float*)d_in[14];
    const float* fc_b = (const float*)d_in[15];
    float* out = (float*)d_out;

    const size_t sm1 = (size_t)(2*N_*KHP_ + 2*F_*KH_ + 2*KH_ + N_*F_ + E_*K_) * 4
                     + (size_t)(2*E_ + (N_+1) + E_) * 4;
    const size_t sm2 = (size_t)(N_*KH_ + 2*N_*KHP_ + KH_ + H_ + E_*K_) * 4
                     + (size_t)(2*E_ + (N_+1) + E_) * 4;
    const size_t sml = SW_BYTES + (2*LH_ + LROWS + 32) * 4;

    cudaFuncSetAttribute(gat1_kernel, cudaFuncAttributeMaxDynamicSharedMemorySize, (int)sm1);
    cudaFuncSetAttribute(gat2_kernel, cudaFuncAttributeMaxDynamicSharedMemorySize, (int)sm2);
    cudaFuncSetAttribute(lstm_cluster_kernel, cudaFuncAttributeMaxDynamicSharedMemorySize, (int)sml);
    cudaFuncSetAttribute(lstm_cluster_kernel, cudaFuncAttributeNonPortableClusterSizeAllowed, 1);

    build_csr_kernel<<<1, 64>>>(ei);
    gat1_kernel<<<G_, 256, sm1>>>(x, ei, Wl1, Wr1, att1, b1);
    gat2_kernel<<<G_, 256, sm2>>>(ei, Wl2, Wr2, att2, b2);
    dim3 gx(G4_/BN, G_/BM);
    xw_gemm_kernel<<<gx, 256>>>(W_ih, b_ih, b_hh);

    {
        cudaLaunchConfig_t cfg = {};
        cfg.gridDim  = dim3(B_*CLU, 1, 1);     // 64 CTAs = 4 clusters of 16
        cfg.blockDim = dim3(128, 1, 1);
        cfg.dynamicSmemBytes = sml;
        cfg.stream = 0;
        cudaLaunchAttribute attrs[1];
        attrs[0].id = cudaLaunchAttributeClusterDimension;
        attrs[0].val.clusterDim.x = CLU;
        attrs[0].val.clusterDim.y = 1;
        attrs[0].val.clusterDim.z = 1;
        cfg.attrs = attrs;
        cfg.numAttrs = 1;
        cudaLaunchKernelEx(&cfg, lstm_cluster_kernel, W_hh);
    }

    fc_kernel<<<1, 32>>>(fc_w, fc_b, out);
}

// round 13
// speedup vs baseline: 1.3509x; 1.1056x over previous
#include <cuda_runtime.h>
#include <cuda_fp16.h>
#include <math.h>

#define B_ 4
#define T_ 256
#define N_ 48
#define F_ 4
#define H_ 64
#define K_ 4
#define E_ 192
#define LH_ 512
#define C_ 8
#define G_ (B_*T_)     // 1024
#define KH_ (K_*H_)    // 256
#define KHP_ (KH_+1)
#define NH_ (N_*H_)    // 3072
#define G4_ (4*LH_)    // 2048
#define NEG_SLOPE 0.2f

#define CLU 16                 // CTAs per cluster (one cluster per batch)
#define LROWS 128              // W rows per CTA (32 j x 4 gates)
#define WSTR 528               // halfs per W row (2 sections of 264)
#define HSEC 264               // floats per h half-section
#define SW_BYTES (LROWS*WSTR*2)   // 135168

// ---------------- scratch ----------------------------------------------------
__device__ float g_h1[G_*N_*KH_];
__device__ float g_seq[G_*NH_];
__device__ float g_xw[G_*G4_];
__device__ float g_hbuf[2][B_][LH_];
__device__ int   g_coff[N_+1];
__device__ int   g_ceid[E_];

// ---------------- deterministic CSR build ------------------------------------
__global__ void build_csr_kernel(const int* __restrict__ ei)
{
    __shared__ int sdst[E_];
    __shared__ int sdeg[N_];
    __shared__ int soff[N_+1];
    int tid = threadIdx.x;
    for (int e = tid; e < E_; e += blockDim.x) sdst[e] = ei[E_ + e];
    __syncthreads();
    for (int n = tid; n < N_; n += blockDim.x) {
        int d = 0;
        for (int e = 0; e < E_; e++) d += (sdst[e] == n);
        sdeg[n] = d;
    }
    __syncthreads();
    if (tid == 0) {
        int acc = 0;
        for (int n = 0; n < N_; n++) { soff[n] = acc; acc += sdeg[n]; }
        soff[N_] = acc;
    }
    __syncthreads();
    for (int n = tid; n < N_; n += blockDim.x) {
        int p = soff[n];
        for (int e = 0; e < E_; e++) if (sdst[e] == n) g_ceid[p++] = e;
    }
    for (int n = tid; n <= N_; n += blockDim.x) g_coff[n] = soff[n];
}

// ---------------- GAT layer 1 ------------------------------------------------
__global__ __launch_bounds__(256) void gat1_kernel(
    const float* __restrict__ x, const int* __restrict__ ei,
    const float* __restrict__ Wl, const float* __restrict__ Wr,
    const float* __restrict__ att, const float* __restrict__ bias)
{
    extern __shared__ float sm[];
    float* xl   = sm;
    float* xr   = xl + N_*KHP_;
    float* wl   = xr + N_*KHP_;
    float* wr   = wl + F_*KH_;
    float* satt = wr + F_*KH_;
    float* sb   = satt + KH_;
    float* sx   = sb + KH_;
    float* se   = sx + N_*F_;
    int* ssrc = (int*)(se + E_*K_);
    int* sdst = ssrc + E_;
    int* soff = sdst + E_;
    int* seid = soff + (N_+1);

    int g = blockIdx.x;
    int tid = threadIdx.x;

    for (int i = tid; i < F_*KH_; i += 256) { wl[i] = Wl[i]; wr[i] = Wr[i]; }
    satt[tid] = att[tid];
    sb[tid] = bias[tid];
    for (int i = tid; i < N_*F_; i += 256) sx[i] = x[(size_t)g*N_*F_ + i];
    for (int i = tid; i < E_; i += 256) { ssrc[i] = ei[i]; sdst[i] = ei[E_+i]; seid[i] = g_ceid[i]; }
    for (int i = tid; i <= N_; i += 256) soff[i] = g_coff[i];
    __syncthreads();

    const int o = tid;
    for (int n = 0; n < N_; n++) {
        float al = 0.f, ar = 0.f;
        #pragma unroll
        for (int f = 0; f < F_; f++) {
            float xv = sx[n*F_ + f];
            al += xv * wl[f*KH_ + o];
            ar += xv * wr[f*KH_ + o];
        }
        xl[n*KHP_ + o] = al;
        xr[n*KHP_ + o] = ar;
    }
    __syncthreads();

    for (int idx = tid; idx < E_*K_; idx += 256) {
        int e = idx >> 2, k = idx & 3;
        const float* pl = xl + ssrc[e]*KHP_ + k*H_;
        const float* pr = xr + sdst[e]*KHP_ + k*H_;
        const float* pa = satt + k*H_;
        float acc = 0.f;
        #pragma unroll 8
        for (int h = 0; h < H_; h++) {
            float v = pl[h] + pr[h];
            v = v > 0.f ? v : NEG_SLOPE * v;
            acc += v * pa[h];
        }
        se[idx] = acc;
    }
    __syncthreads();

    for (int idx = tid; idx < N_*K_; idx += 256) {
        int n = idx >> 2, k = idx & 3;
        int a0 = soff[n], a1 = soff[n+1];
        float mx = -1e30f;
        for (int a = a0; a < a1; a++) mx = fmaxf(mx, se[seid[a]*K_ + k]);
        float s = 0.f;
        for (int a = a0; a < a1; a++) s += expf(se[seid[a]*K_ + k] - mx);
        float inv = 1.f / (s + 1e-16f);
        for (int a = a0; a < a1; a++) {
            int j = seid[a]*K_ + k;
            se[j] = expf(se[j] - mx) * inv;
        }
    }
    __syncthreads();

    int k = o >> 6;
    float* outp = g_h1 + (size_t)g*N_*KH_;
    for (int n = 0; n < N_; n++) {
        int a0 = soff[n], a1 = soff[n+1];
        float acc = 0.f;
        for (int a = a0; a < a1; a++) {
            int e = seid[a];
            acc += se[e*K_ + k] * xl[ssrc[e]*KHP_ + o];
        }
        outp[n*KH_ + o] = fmaxf(acc + sb[o], 0.f);
    }
}

// ---------------- GAT layer 2 (fused fp32, proven) ----------------------------
__global__ __launch_bounds__(256) void gat2_kernel(
    const int* __restrict__ ei,
    const float* __restrict__ Wl, const float* __restrict__ Wr,
    const float* __restrict__ att, const float* __restrict__ bias)
{
    extern __shared__ float sm[];
    float* sh_in = sm;
    float* xl    = sh_in + N_*KH_;
    float* xr    = xl + N_*KHP_;
    float* satt  = xr + N_*KHP_;
    float* sb    = satt + KH_;
    float* se    = sb + H_;
    int* ssrc = (int*)(se + E_*K_);
    int* sdst = ssrc + E_;
    int* soff = sdst + E_;
    int* seid = soff + (N_+1);

    int g = blockIdx.x;
    int tid = threadIdx.x;

    const float* h1p = g_h1 + (size_t)g*N_*KH_;
    for (int i = tid; i < N_*KH_; i += 256) sh_in[i] = h1p[i];
    satt[tid] = att[tid];
    if (tid < H_) sb[tid] = bias[tid];
    for (int i = tid; i < E_; i += 256) { ssrc[i] = ei[i]; sdst[i] = ei[E_+i]; seid[i] = g_ceid[i]; }
    for (int i = tid; i <= N_; i += 256) soff[i] = g_coff[i];
    __syncthreads();

    const int o = tid;
    {
        float acc[N_];
        #pragma unroll
        for (int n = 0; n < N_; n++) acc[n] = 0.f;
        #pragma unroll 2
        for (int i = 0; i < KH_; i++) {
            float w = Wl[i*KH_ + o];
            #pragma unroll
            for (int n = 0; n < N_; n++) acc[n] += sh_in[n*KH_ + i] * w;
        }
        #pragma unroll
        for (int n = 0; n < N_; n++) xl[n*KHP_ + o] = acc[n];
    }
    {
        float acc[N_];
        #pragma unroll
        for (int n = 0; n < N_; n++) acc[n] = 0.f;
        #pragma unroll 2
        for (int i = 0; i < KH_; i++) {
            float w = Wr[i*KH_ + o];
            #pragma unroll
            for (int n = 0; n < N_; n++) acc[n] += sh_in[n*KH_ + i] * w;
        }
        #pragma unroll
        for (int n = 0; n < N_; n++) xr[n*KHP_ + o] = acc[n];
    }
    __syncthreads();

    for (int idx = tid; idx < E_*K_; idx += 256) {
        int e = idx >> 2, k = idx & 3;
        const float* pl = xl + ssrc[e]*KHP_ + k*H_;
        const float* pr = xr + sdst[e]*KHP_ + k*H_;
        const float* pa = satt + k*H_;
        float acc = 0.f;
        #pragma unroll 8
        for (int h = 0; h < H_; h++) {
            float v = pl[h] + pr[h];
            v = v > 0.f ? v : NEG_SLOPE * v;
            acc += v * pa[h];
        }
        se[idx] = acc;
    }
    __syncthreads();

    for (int idx = tid; idx < N_*K_; idx += 256) {
        int n = idx >> 2, k = idx & 3;
        int a0 = soff[n], a1 = soff[n+1];
        float mx = -1e30f;
        for (int a = a0; a < a1; a++) mx = fmaxf(mx, se[seid[a]*K_ + k]);
        float s = 0.f;
        for (int a = a0; a < a1; a++) s += expf(se[seid[a]*K_ + k] - mx);
        float inv = 1.f / (s + 1e-16f);
        for (int a = a0; a < a1; a++) {
            int j = seid[a]*K_ + k;
            se[j] = expf(se[j] - mx) * inv;
        }
    }
    __syncthreads();

    for (int idx = tid; idx < N_*H_; idx += 256) {
        int n = idx >> 6, h = idx & 63;
        int a0 = soff[n], a1 = soff[n+1];
        float acc = 0.f;
        for (int a = a0; a < a1; a++) {
            int e = seid[a]; int s = ssrc[e];
            #pragma unroll
            for (int k2 = 0; k2 < K_; k2++)
                acc += se[e*K_ + k2] * xl[s*KHP_ + k2*H_ + h];
        }
        float v = acc * 0.25f + sb[h];
        g_seq[(size_t)g*NH_ + n*H_ + h] = fmaxf(v, 0.f);
    }
}

// ---------------- xw GEMM (proven 64x64x32 fp32) ------------------------------
#define BM 64
#define BN 64
#define BK 32
#define BMP (BM+4)
#define BNP (BN+4)
__global__ __launch_bounds__(256) void xw_gemm_kernel(
    const float* __restrict__ W_ih,
    const float* __restrict__ b_ih, const float* __restrict__ b_hh)
{
    __shared__ float As[BK][BMP];
    __shared__ float Bs[BK][BNP];
    int bn = blockIdx.x, bm = blockIdx.y;
    int tid = threadIdx.x;
    int tx = tid & 15, ty = tid >> 4;
    float acc[4][4] = {};
    const float* A0 = g_seq + (size_t)(bm*BM)*NH_;
    const float* B0 = W_ih + (size_t)(bn*BN)*NH_;
    int lr = tid >> 3;
    int lc = (tid & 7) * 4;

    for (int k0 = 0; k0 < NH_; k0 += BK) {
        #pragma unroll
        for (int half = 0; half < 2; half++) {
            int r = lr + half*32;
            float4 a4 = *(const float4*)&A0[(size_t)r*NH_ + k0 + lc];
            As[lc+0][r] = a4.x; As[lc+1][r] = a4.y;
            As[lc+2][r] = a4.z; As[lc+3][r] = a4.w;
            float4 b4 = *(const float4*)&B0[(size_t)r*NH_ + k0 + lc];
            Bs[lc+0][r] = b4.x; Bs[lc+1][r] = b4.y;
            Bs[lc+2][r] = b4.z; Bs[lc+3][r] = b4.w;
        }
        __syncthreads();
        #pragma unroll
        for (int k = 0; k < BK; k++) {
            float4 av = *(const float4*)&As[k][ty*4];
            float4 bv = *(const float4*)&Bs[k][tx*4];
            float a[4] = {av.x, av.y, av.z, av.w};
            float b[4] = {bv.x, bv.y, bv.z, bv.w};
            #pragma unroll
            for (int i = 0; i < 4; i++)
                #pragma unroll
                for (int j = 0; j < 4; j++)
                    acc[i][j] += a[i] * b[j];
        }
        __syncthreads();
    }
    #pragma unroll
    for (int i = 0; i < 4; i++) {
        int r = bm*BM + ty*4 + i;
        int c = bn*BN + tx*4;
        float4 o;
        o.x = acc[i][0] + b_ih[c+0] + b_hh[c+0];
        o.y = acc[i][1] + b_ih[c+1] + b_hh[c+1];
        o.z = acc[i][2] + b_ih[c+2] + b_hh[c+2];
        o.w = acc[i][3] + b_ih[c+3] + b_hh[c+3];
        *(float4*)&g_xw[(size_t)r*G4_ + c] = o;
    }
}

// ---------------- cluster LSTM v2: 256 thr, vectorized fp16 W, fused bcast ----
__device__ __forceinline__ float sigm(float x) { return 1.f / (1.f + expf(-x)); }

__device__ __forceinline__ unsigned smem_u32(const void* p)
{
    unsigned a;
    asm("{ .reg .u64 t; cvta.to.shared.u64 t, %1; cvt.u32.u64 %0, t; }"
        : "=r"(a) : "l"(p));
    return a;
}
__device__ __forceinline__ unsigned my_cluster_rank()
{
    unsigned r;
    asm("mov.u32 %0, %%cluster_ctarank;" : "=r"(r));
    return r;
}
__device__ __forceinline__ void dsmem_store_f32(unsigned laddr, unsigned rank, float v)
{
    asm volatile(
        "{ .reg .b32 ra; mapa.shared::cluster.u32 ra, %0, %1; "
        "st.shared::cluster.f32 [ra], %2; }"
        :: "r"(laddr), "r"(rank), "f"(v) : "memory");
}

__global__ __launch_bounds__(256, 1) void lstm_cluster_kernel(const float* __restrict__ W_hh)
{
    extern __shared__ char smc[];
    __half* sw  = (__half*)smc;                  // [128][2][264] halfs
    float* hbuf = (float*)(smc + SW_BYTES);      // [2][2*HSEC] floats
    float* sval = hbuf + 2*(2*HSEC);             // 128

    const int tid  = threadIdx.x;
    const int b    = blockIdx.x / CLU;
    const unsigned rank = my_cluster_rank();     // 0..15
    const int j0   = rank * 32;

    // load W slice as fp16 into [row][half][264] layout
    for (int idx = tid; idx < LROWS*256; idx += 256) {
        int r  = idx >> 8;            // row 0..127
        int i2 = idx & 255;           // half2 index within row (512 halfs)
        int gate = r >> 5, jr = r & 31;
        float2 wv = *(const float2*)&W_hh[(size_t)(gate*LH_ + j0 + jr)*LH_ + i2*2];
        int e  = i2*2;
        int hf = e >> 8, k = e & 255;
        *(__half2*)&sw[r*WSTR + hf*HSEC + k] = __floats2half2_rn(wv.x, wv.y);
    }
    for (int i = tid; i < 2*HSEC; i += 256) hbuf[i] = 0.f;   // h buffer 0
    __syncthreads();

    const int row = tid >> 1, hf = tid & 1;
    const int gate = row >> 5, jr = row & 31;
    const uint4* wv = (const uint4*)(sw + row*WSTR + hf*HSEC);   // 32 x 8 halfs
    const float* xp = g_xw + (size_t)(b*T_)*G4_ + gate*LH_ + j0 + jr;
    const unsigned hbuf_addr = smem_u32(hbuf);

    float xval = __ldcg(xp);
    float c = 0.f;                               // cell state (tid < 32)

    for (int t = 0; t < T_; t++) {
        const float4* hv = (const float4*)(hbuf + (t & 1)*(2*HSEC) + hf*HSEC);
        float a0 = 0.f, a1 = 0.f, a2 = 0.f, a3 = 0.f;
        #pragma unroll 4
        for (int i = 0; i < 32; i++) {
            uint4 w = wv[i];
            float4 p = hv[2*i], q = hv[2*i+1];
            float2 w0 = __half22float2(*(__half2*)&w.x);
            float2 w1 = __half22float2(*(__half2*)&w.y);
            float2 w2 = __half22float2(*(__half2*)&w.z);
            float2 w3 = __half22float2(*(__half2*)&w.w);
            a0 = fmaf(w0.x, p.x, a0); a1 = fmaf(w0.y, p.y, a1);
            a2 = fmaf(w1.x, p.z, a2); a3 = fmaf(w1.y, p.w, a3);
            a0 = fmaf(w2.x, q.x, a0); a1 = fmaf(w2.y, q.y, a1);
            a2 = fmaf(w3.x, q.z, a2); a3 = fmaf(w3.y, q.w, a3);
        }
        float s = (a0 + a1) + (a2 + a3);
        s += __shfl_xor_sync(0xffffffffu, s, 1);   // combine the two halves
        if (hf == 0) sval[row] = s + xval;
        __syncthreads();

        if (tid < 32) {
            float gi = sval[tid];
            float gf = sval[32 + tid];
            float gg = sval[64 + tid];
            float go = sval[96 + tid];
            c = sigm(gf)*c + sigm(gi)*tanhf(gg);
            float h = sigm(go)*tanhf(c);
            if (t == T_-1) {
                g_hbuf[0][b][j0 + tid] = h;
            } else {
                int jg = j0 + tid;
                int hfd = jg >> 8, kd = jg & 255;
                unsigned dst = hbuf_addr + (unsigned)(((t + 1) & 1)*(2*HSEC) + hfd*HSEC + kd)*4u;
                #pragma unroll
                for (int q = 0; q < CLU; q++)
                    dsmem_store_f32(dst, (unsigned)q, h);
            }
        }
        if (t < T_-1) {
            xval = __ldcg(xp + (size_t)(t + 1)*G4_);  // prefetch next x
            asm volatile("barrier.cluster.arrive.aligned;" ::: "memory");
            asm volatile("barrier.cluster.wait.aligned;" ::: "memory");
        }
    }
    asm volatile("barrier.cluster.arrive.aligned;" ::: "memory");
    asm volatile("barrier.cluster.wait.aligned;" ::: "memory");
}

// ---------------- final fc -----------------------------------------------------
__global__ void fc_kernel(const float* __restrict__ fc_w,
                          const float* __restrict__ fc_b,
                          float* __restrict__ out)
{
    int tid = threadIdx.x;
    if (tid < B_*C_) {
        int b = tid >> 3, c = tid & 7;
        const float* h = g_hbuf[0][b];
        const float* w = fc_w + c*LH_;
        float acc = 0.f;
        for (int j = 0; j < LH_; j++) acc += h[j] * w[j];
        out[b*C_ + c] = acc + fc_b[c];
    }
}

// ---------------- launch -------------------------------------------------------
extern "C" void kernel_launch(void* const* d_in, const int* in_sizes, int n_in,
                              void* d_out, int out_size)
{
    (void)in_sizes; (void)n_in; (void)out_size;
    const float* x    = (const float*)d_in[0];
    const int*   ei   = (const int*)d_in[1];
    const float* Wl1  = (const float*)d_in[2];
    const float* Wr1  = (const float*)d_in[3];
    const float* att1 = (const float*)d_in[4];
    const float* b1   = (const float*)d_in[5];
    const float* Wl2  = (const float*)d_in[6];
    const float* Wr2  = (const float*)d_in[7];
    const float* att2 = (const float*)d_in[8];
    const float* b2   = (const float*)d_in[9];
    const float* W_ih = (const float*)d_in[10];
    const float* W_hh = (const float*)d_in[11];
    const float* b_ih = (const float*)d_in[12];
    const float* b_hh = (const float*)d_in[13];
    const float* fc_w = (const float*)d_in[14];
    const float* fc_b = (const float*)d_in[15];
    float* out = (float*)d_out;

    const size_t sm1 = (size_t)(2*N_*KHP_ + 2*F_*KH_ + 2*KH_ + N_*F_ + E_*K_) * 4
                     + (size_t)(2*E_ + (N_+1) + E_) * 4;
    const size_t sm2 = (size_t)(N_*KH_ + 2*N_*KHP_ + KH_ + H_ + E_*K_) * 4
                     + (size_t)(2*E_ + (N_+1) + E_) * 4;
    const size_t sml = SW_BYTES + (size_t)(2*(2*HSEC) + LROWS) * 4;

    cudaFuncSetAttribute(gat1_kernel, cudaFuncAttributeMaxDynamicSharedMemorySize, (int)sm1);
    cudaFuncSetAttribute(gat2_kernel, cudaFuncAttributeMaxDynamicSharedMemorySize, (int)sm2);
    cudaFuncSetAttribute(lstm_cluster_kernel, cudaFuncAttributeMaxDynamicSharedMemorySize, (int)sml);
    cudaFuncSetAttribute(lstm_cluster_kernel, cudaFuncAttributeNonPortableClusterSizeAllowed, 1);

    build_csr_kernel<<<1, 64>>>(ei);
    gat1_kernel<<<G_, 256, sm1>>>(x, ei, Wl1, Wr1, att1, b1);
    gat2_kernel<<<G_, 256, sm2>>>(ei, Wl2, Wr2, att2, b2);
    dim3 gx(G4_/BN, G_/BM);
    xw_gemm_kernel<<<gx, 256>>>(W_ih, b_ih, b_hh);

    {
        cudaLaunchConfig_t cfg = {};
        cfg.gridDim  = dim3(B_*CLU, 1, 1);     // 64 CTAs = 4 clusters of 16
        cfg.blockDim = dim3(256, 1, 1);
        cfg.dynamicSmemBytes = sml;
        cfg.stream = 0;
        cudaLaunchAttribute attrs[1];
        attrs[0].id = cudaLaunchAttributeClusterDimension;
        attrs[0].val.clusterDim.x = CLU;
        attrs[0].val.clusterDim.y = 1;
        attrs[0].val.clusterDim.z = 1;
        cfg.attrs = attrs;
        cfg.numAttrs = 1;
        cudaLaunchKernelEx(&cfg, lstm_cluster_kernel, W_hh);
    }

    fc_kernel<<<1, 32>>>(fc_w, fc_b, out);
}